// round 9
// baseline (speedup 1.0000x reference)
#include <cuda_runtime.h>

// Fused Canny-NMS-dilate for (32,3,512,512) fp32 -> (32,1,512,512) fp32.
// 64x32 tile, 256 threads (32x8). Interior tiles clamp-free; stages 2+3 fused
// into a register rolling-window pass (no h-blur smem buffer).

#define H 512
#define W 512
#define PLANE (512 * 512)

struct __align__(16) Smem {
    float bufA[44 * 84];   // gray (stride 84) -> mag (stride 72) -> rowmax (stride 64)
    float bufC[40 * 72];   // blur (stride 72) -> mask (stride 72)
    short sDel[38 * 72];   // NMS neighbor offset (sign-free)
};

__device__ __forceinline__ void mag_sector(float gx, float gy, float& m, short& e) {
    m = sqrtf(fmaf(gx, gx, fmaf(gy, gy, 1e-6f)));
    float ax = fabsf(gx), ay = fabsf(gy);
    if (ay <= 0.41421356237309503f * ax)      e = 1;    // horizontal
    else if (ay >= 2.4142135623730951f * ax)  e = 72;   // vertical
    else e = ((gx > 0.0f) == (gy > 0.0f)) ? 73 : 71;    // diagonals
}

template <bool BORDER>
__device__ __forceinline__ void canny_tile(
    Smem& s, const float* __restrict__ base, float* __restrict__ ob,
    int x0, int y0, int tx, int ty, int tid) {

    const float w0 = 0.054488684549642945f;
    const float w1 = 0.24420134200323337f;
    const float w2 = 0.4026199485882447f;

    // ---- Stage 1: gray (44 x 76) into bufA stride 84 ----
    if (BORDER) {
        int xs0, xs1, xs2;
        int x = x0 - 6 + tx; x = (x < 0) ? -x : x; xs0 = (x > 511) ? 1022 - x : x;
        x = x0 + 26 + tx;                           xs1 = (x > 511) ? 1022 - x : x;
        x = x0 + 58 + tx;                           xs2 = (x > 511) ? 1022 - x : x;
        for (int i = ty; i < 44; i += 8) {
            int y = y0 - 6 + i; y = (y < 0) ? -y : y; y = (y > 511) ? 1022 - y : y;
            const float* r0 = base + y * W;
            float* gr = &s.bufA[i * 84];
            gr[tx]      = fmaf(0.299f, r0[2 * PLANE + xs0], fmaf(0.587f, r0[PLANE + xs0], 0.114f * r0[xs0]));
            gr[tx + 32] = fmaf(0.299f, r0[2 * PLANE + xs1], fmaf(0.587f, r0[PLANE + xs1], 0.114f * r0[xs1]));
            if (tx < 12)
                gr[tx + 64] = fmaf(0.299f, r0[2 * PLANE + xs2], fmaf(0.587f, r0[PLANE + xs2], 0.114f * r0[xs2]));
        }
    } else {
        for (int i = ty; i < 44; i += 8) {
            const float* r0 = base + (y0 - 6 + i) * W + (x0 - 6);
            float2* gr = (float2*)&s.bufA[i * 84];
            {
                float2 b = *(const float2*)(r0 + 2 * tx);
                float2 g = *(const float2*)(r0 + PLANE + 2 * tx);
                float2 r = *(const float2*)(r0 + 2 * PLANE + 2 * tx);
                gr[tx] = make_float2(fmaf(0.299f, r.x, fmaf(0.587f, g.x, 0.114f * b.x)),
                                     fmaf(0.299f, r.y, fmaf(0.587f, g.y, 0.114f * b.y)));
            }
            if (tx < 6) {
                float2 b = *(const float2*)(r0 + 64 + 2 * tx);
                float2 g = *(const float2*)(r0 + PLANE + 64 + 2 * tx);
                float2 r = *(const float2*)(r0 + 2 * PLANE + 64 + 2 * tx);
                gr[32 + tx] = make_float2(fmaf(0.299f, r.x, fmaf(0.587f, g.x, 0.114f * b.x)),
                                          fmaf(0.299f, r.y, fmaf(0.587f, g.y, 0.114f * b.y)));
            }
        }
    }
    __syncthreads();

    // ---- Stage 2+3 fused: h-blur in registers (rolling 5-row window) -> v-blur ----
    // 4 row-groups of 10 blur rows; warps 0-3 cover float2 cols 0..31,
    // warp 4 (16 lanes) covers float2 cols 32..35 for all 4 groups.
    {
        int g = -1, c = 0;
        if (ty < 4)                       { g = ty;      c = tx; }
        else if (ty == 4 && tx < 16)      { g = tx >> 2; c = 32 + (tx & 3); }
        if (g >= 0) {
            const int g10 = g * 10;
            float2 win[5];
#pragma unroll
            for (int k = 0; k < 14; ++k) {
                const float2* g2 = (const float2*)&s.bufA[(g10 + k) * 84];
                float2 e0 = g2[c], e1 = g2[c + 1], e2 = g2[c + 2];
                float2 h;
                h.x = fmaf(w0, e0.x + e2.x, fmaf(w1, e0.y + e1.y, w2 * e1.x));
                h.y = fmaf(w0, e0.y + e2.y, fmaf(w1, e1.x + e2.x, w2 * e1.y));
                win[k % 5] = h;
                if (k >= 4) {
                    float2 a  = win[(k - 4) % 5], b2 = win[(k - 3) % 5];
                    float2 cc = win[(k - 2) % 5], d  = win[(k - 1) % 5];
                    float2 o;
                    o.x = fmaf(w0, a.x + h.x, fmaf(w1, b2.x + d.x, w2 * cc.x));
                    o.y = fmaf(w0, a.y + h.y, fmaf(w1, b2.y + d.y, w2 * cc.y));
                    ((float2*)&s.bufC[(g10 + k - 4) * 72])[c] = o;
                }
            }
        }
    }
    __syncthreads();

    // ---- Stage 4a: Sobel + mag + delta, cols 0..63 (rolling stream) -> bufA ----
    {
        const int r0m = min(ty * 5, 33);   // ragged tail: duplicate rows, harmless
        const int jb = 2 * tx;
        const int x = x0 - 3 + jb;
        bool xin0 = true, xin1 = true, lc0 = true, rc0 = true, lc1 = true, rc1 = true;
        if (BORDER) {
            xin0 = (unsigned)x < (unsigned)W;
            xin1 = (unsigned)(x + 1) < (unsigned)W;
            lc0 = (x > 0); rc0 = (x < W - 1);
            lc1 = (x + 1 > 0); rc1 = (x + 1 < W - 1);
        }
        float s0p, d0p, s1p, d1p, s0c, d0c, s1c, d1c;
#define LOADROW(R, S0, D0, S1, D1)                                             \
        {                                                                      \
            int rr;                                                            \
            if (BORDER) {                                                      \
                int yr = y0 - 3 + r0m + (R);                                   \
                yr = max(0, min(yr, H - 1));                                   \
                rr = yr - y0 + 4;                                              \
            } else {                                                           \
                rr = r0m + (R) + 1;                                            \
            }                                                                  \
            const float2* br = (const float2*)&s.bufC[rr * 72 + jb];           \
            float2 p = br[0], q = br[1];                                       \
            float l0 = BORDER ? (lc0 ? p.x : p.y) : p.x;                       \
            float r0_ = BORDER ? (rc0 ? q.x : p.y) : q.x;                      \
            float l1 = BORDER ? (lc1 ? p.y : q.x) : p.y;                       \
            float r1_ = BORDER ? (rc1 ? q.y : q.x) : q.y;                      \
            S0 = l0 + 2.0f * p.y + r0_; D0 = r0_ - l0;                         \
            S1 = l1 + 2.0f * q.x + r1_; D1 = r1_ - l1;                         \
        }
        LOADROW(-1, s0p, d0p, s1p, d1p)
        LOADROW(0, s0c, d0c, s1c, d1c)
#pragma unroll
        for (int v = 0; v < 5; ++v) {
            float s0n, d0n, s1n, d1n;
            LOADROW(v + 1, s0n, d0n, s1n, d1n)
            const int i = r0m + v;
            float gy0 = (s0n - s0p) * 0.125f;
            float gx0 = (d0p + 2.0f * d0c + d0n) * 0.125f;
            float gy1 = (s1n - s1p) * 0.125f;
            float gx1 = (d1p + 2.0f * d1c + d1n) * 0.125f;

            float m0 = 0.0f, m1 = 0.0f;
            short e0 = 1, e1 = 1;
            if (BORDER) {
                bool yin = (unsigned)(y0 - 3 + i) < (unsigned)H;
                if (yin && xin0) mag_sector(gx0, gy0, m0, e0);
                if (yin && xin1) mag_sector(gx1, gy1, m1, e1);
            } else {
                mag_sector(gx0, gy0, m0, e0);
                mag_sector(gx1, gy1, m1, e1);
            }
            *(float2*)&s.bufA[i * 72 + jb] = make_float2(m0, m1);
            *(short2*)&s.sDel[i * 72 + jb] = make_short2(e0, e1);

            s0p = s0c; d0p = d0c; s1p = s1c; d1p = d1c;
            s0c = s0n; d0c = d0n; s1c = s1n; d1c = d1n;
        }
#undef LOADROW
    }

    // ---- Stage 4b: cols 64..69 as flat tasks (38 rows x 3 float2 = 114) ----
    if (tid < 114) {
        const int i = tid / 3;
        const int c = tid - 3 * i;
        const int jb = 64 + 2 * c;
        float m0 = 0.0f, m1 = 0.0f;
        short e0 = 1, e1 = 1;
        if (BORDER) {
            const int y = y0 - 3 + i;
            if ((unsigned)y < (unsigned)H) {
                int ymi = max(y - 1, 0) - (y0 - 4);
                int ypi = min(y + 1, H - 1) - (y0 - 4);
                int yci = i + 1;
#pragma unroll
                for (int k = 0; k < 2; ++k) {
                    int xk = x0 - 3 + jb + k;
                    if ((unsigned)xk < (unsigned)W) {
                        int xm = max(xk - 1, 0) - (x0 - 4);
                        int xp = min(xk + 1, W - 1) - (x0 - 4);
                        int xc = jb + 1 + k;
                        float b00 = s.bufC[ymi * 72 + xm], b01 = s.bufC[ymi * 72 + xc], b02 = s.bufC[ymi * 72 + xp];
                        float b10 = s.bufC[yci * 72 + xm],                              b12 = s.bufC[yci * 72 + xp];
                        float b20 = s.bufC[ypi * 72 + xm], b21 = s.bufC[ypi * 72 + xc], b22 = s.bufC[ypi * 72 + xp];
                        float gx = ((b02 - b00) + 2.0f * (b12 - b10) + (b22 - b20)) * 0.125f;
                        float gy = ((b20 - b00) + 2.0f * (b21 - b01) + (b22 - b02)) * 0.125f;
                        if (k == 0) mag_sector(gx, gy, m0, e0);
                        else        mag_sector(gx, gy, m1, e1);
                    }
                }
            }
        } else {
            const float2* rU = (const float2*)&s.bufC[i * 72 + jb];
            const float2* rC = (const float2*)&s.bufC[(i + 1) * 72 + jb];
            const float2* rD = (const float2*)&s.bufC[(i + 2) * 72 + jb];
            float2 u01 = rU[0], u23 = rU[1];
            float2 c01 = rC[0], c23 = rC[1];
            float2 d01 = rD[0], d23 = rD[1];
            float gx0 = ((u23.x - u01.x) + 2.0f * (c23.x - c01.x) + (d23.x - d01.x)) * 0.125f;
            float gy0 = ((d01.x - u01.x) + 2.0f * (d01.y - u01.y) + (d23.x - u23.x)) * 0.125f;
            float gx1 = ((u23.y - u01.y) + 2.0f * (c23.y - c01.y) + (d23.y - d01.y)) * 0.125f;
            float gy1 = ((d01.y - u01.y) + 2.0f * (d23.x - u23.x) + (d23.y - u23.y)) * 0.125f;
            mag_sector(gx0, gy0, m0, e0);
            mag_sector(gx1, gy1, m1, e1);
        }
        *(float2*)&s.bufA[i * 72 + jb] = make_float2(m0, m1);
        *(short2*)&s.sDel[i * 72 + jb] = make_short2(e0, e1);
    }
    __syncthreads();

    // ---- Stage 5: NMS mask (36 x 68) -> bufC (blur dead) ----
    for (int i = ty; i < 36; i += 8) {
        bool yin = true;
        if (BORDER) yin = (unsigned)(y0 - 2 + i) < (unsigned)H;
#pragma unroll
        for (int jj = 0; jj < 3; ++jj) {
            int j = tx + jj * 32;
            if (jj < 2 || tx < 4) {
                float m = 0.0f;
                bool ok = true;
                if (BORDER) ok = yin && (unsigned)(x0 - 2 + j) < (unsigned)W;
                if (ok) {
                    int ci = (i + 1) * 72 + j + 1;
                    int d = s.sDel[ci];
                    float c = s.bufA[ci];
                    float p1 = s.bufA[ci + d];
                    float p2 = s.bufA[ci - d];
                    m = (c > p1 && c > p2) ? c : 0.0f;
                }
                s.bufC[i * 72 + j] = m;
            }
        }
    }
    __syncthreads();

    // ---- Stage 6: horizontal 5-max (36 x 64), float4 -> bufA (mag dead) ----
    {
        const int half = tx >> 4;
        const int q4 = (tx & 15) * 4;
        for (int r = ty; r < 18; r += 8) {
            const int i = half * 18 + r;
            float4 A = *(const float4*)&s.bufC[i * 72 + q4];
            float4 B = *(const float4*)&s.bufC[i * 72 + q4 + 4];
            float m  = fmaxf(A.w, B.x);
            float t1 = fmaxf(A.y, A.z);
            float t2 = fmaxf(B.y, B.z);
            float4 o;
            o.x = fmaxf(m, fmaxf(A.x, t1));
            o.y = fmaxf(m, fmaxf(t1, B.y));
            o.z = fmaxf(m, fmaxf(A.z, t2));
            o.w = fmaxf(m, fmaxf(t2, B.w));
            *(float4*)&s.bufA[i * 64 + q4] = o;
        }
    }
    __syncthreads();

    // ---- Stage 7: vertical 5-max, 4 contiguous rows/thread, float2 STG ----
    {
        const int r0o = ty * 4;
        float2 t[8];
#pragma unroll
        for (int r = 0; r < 8; ++r) t[r] = ((const float2*)&s.bufA[(r0o + r) * 64])[tx];
#pragma unroll
        for (int v = 0; v < 4; ++v) {
            float cx = fmaxf(fmaxf(t[v + 1].x, t[v + 2].x), fmaxf(t[v + 3].x, t[v + 4].x));
            float cy = fmaxf(fmaxf(t[v + 1].y, t[v + 2].y), fmaxf(t[v + 3].y, t[v + 4].y));
            float2 o = make_float2(fmaxf(cx, t[v].x), fmaxf(cy, t[v].y));
            *(float2*)&ob[(size_t)(y0 + r0o + v) * W + x0 + 2 * tx] = o;
        }
    }
}

__global__ __launch_bounds__(256) void canny_fused_kernel(
    const float* __restrict__ in, float* __restrict__ out) {
    __shared__ Smem s;
    const int bx = blockIdx.x, by = blockIdx.y;
    const int x0 = bx * 64, y0 = by * 32;
    const float* base = in + (size_t)blockIdx.z * 3 * PLANE;
    float* ob = out + (size_t)blockIdx.z * PLANE;
    const int tx = threadIdx.x & 31;
    const int ty = threadIdx.x >> 5;

    if (bx == 0 || bx == 7 || by == 0 || by == 15)
        canny_tile<true>(s, base, ob, x0, y0, tx, ty, threadIdx.x);
    else
        canny_tile<false>(s, base, ob, x0, y0, tx, ty, threadIdx.x);
}

extern "C" void kernel_launch(void* const* d_in, const int* in_sizes, int n_in,
                              void* d_out, int out_size) {
    const float* x = (const float*)d_in[0];
    float* out = (float*)d_out;
    dim3 grid(W / 64, H / 32, 32);
    canny_fused_kernel<<<grid, 256>>>(x, out);
}

// round 10
// speedup vs baseline: 1.4098x; 1.4098x over previous
#include <cuda_runtime.h>

// Fused Canny-NMS-dilate for (32,3,512,512) fp32 -> (32,1,512,512) fp32.
// 64x32 tile, 256 threads (32x8). R6 stage structure (all warps active in
// every stage) + two-buffer aliasing (31.5KB smem) + launch_bounds(256,6).

#define H 512
#define W 512
#define PLANE (512 * 512)

// bufA: gray 44x76 (stride 80) -> blur 40x72 (stride 72) -> mask 36x68 (stride 72)
// bufB: hblur 44x72 (stride 72) -> mag 38x70 (stride 72) -> rowmax 36x64 (stride 64)
struct __align__(16) Smem {
    float bufA[44 * 80];
    float bufB[44 * 72];
    short sDel[38 * 72];
};

__device__ __forceinline__ void mag_sector(float gx, float gy, float& m, short& e) {
    m = sqrtf(fmaf(gx, gx, fmaf(gy, gy, 1e-6f)));
    float ax = fabsf(gx), ay = fabsf(gy);
    if (ay <= 0.41421356237309503f * ax)      e = 1;    // horizontal
    else if (ay >= 2.4142135623730951f * ax)  e = 72;   // vertical
    else e = ((gx > 0.0f) == (gy > 0.0f)) ? 73 : 71;    // diagonals
}

template <bool BORDER>
__device__ __forceinline__ void canny_tile(
    Smem& s, const float* __restrict__ base, float* __restrict__ ob,
    int x0, int y0, int tx, int ty, int tid) {

    const float w0 = 0.054488684549642945f;
    const float w1 = 0.24420134200323337f;
    const float w2 = 0.4026199485882447f;

    // ---- Stage 1: gray (44 x 76) -> bufA stride 80 ----
    if (BORDER) {
        int xs0, xs1, xs2;
        int x = x0 - 6 + tx; x = (x < 0) ? -x : x; xs0 = (x > 511) ? 1022 - x : x;
        x = x0 + 26 + tx;                           xs1 = (x > 511) ? 1022 - x : x;
        x = x0 + 58 + tx;                           xs2 = (x > 511) ? 1022 - x : x;
        for (int i = ty; i < 44; i += 8) {
            int y = y0 - 6 + i; y = (y < 0) ? -y : y; y = (y > 511) ? 1022 - y : y;
            const float* r0 = base + y * W;
            float* gr = &s.bufA[i * 80];
            gr[tx]      = fmaf(0.299f, r0[2 * PLANE + xs0], fmaf(0.587f, r0[PLANE + xs0], 0.114f * r0[xs0]));
            gr[tx + 32] = fmaf(0.299f, r0[2 * PLANE + xs1], fmaf(0.587f, r0[PLANE + xs1], 0.114f * r0[xs1]));
            if (tx < 12)
                gr[tx + 64] = fmaf(0.299f, r0[2 * PLANE + xs2], fmaf(0.587f, r0[PLANE + xs2], 0.114f * r0[xs2]));
        }
    } else {
        for (int i = ty; i < 44; i += 8) {
            const float* r0 = base + (y0 - 6 + i) * W + (x0 - 6);
            float2* gr = (float2*)&s.bufA[i * 80];
            {
                float2 b = *(const float2*)(r0 + 2 * tx);
                float2 g = *(const float2*)(r0 + PLANE + 2 * tx);
                float2 r = *(const float2*)(r0 + 2 * PLANE + 2 * tx);
                gr[tx] = make_float2(fmaf(0.299f, r.x, fmaf(0.587f, g.x, 0.114f * b.x)),
                                     fmaf(0.299f, r.y, fmaf(0.587f, g.y, 0.114f * b.y)));
            }
            if (tx < 6) {
                float2 b = *(const float2*)(r0 + 64 + 2 * tx);
                float2 g = *(const float2*)(r0 + PLANE + 64 + 2 * tx);
                float2 r = *(const float2*)(r0 + 2 * PLANE + 64 + 2 * tx);
                gr[32 + tx] = make_float2(fmaf(0.299f, r.x, fmaf(0.587f, g.x, 0.114f * b.x)),
                                          fmaf(0.299f, r.y, fmaf(0.587f, g.y, 0.114f * b.y)));
            }
        }
    }
    __syncthreads();

    // ---- Stage 2: horizontal Gaussian (44 x 72) -> bufB, float2 pairs ----
    for (int i = ty; i < 44; i += 8) {
        const float2* g2 = (const float2*)&s.bufA[i * 80];
        float2 e0 = g2[tx], e1 = g2[tx + 1], e2 = g2[tx + 2];
        float2 o;
        o.x = fmaf(w0, e0.x + e2.x, fmaf(w1, e0.y + e1.y, w2 * e1.x));
        o.y = fmaf(w0, e0.y + e2.y, fmaf(w1, e1.x + e2.x, w2 * e1.y));
        ((float2*)&s.bufB[i * 72])[tx] = o;
        if (tx < 8) {
            const float* g = &s.bufA[i * 80 + 64];
            s.bufB[i * 72 + 64 + tx] =
                fmaf(w0, g[tx] + g[tx + 4], fmaf(w1, g[tx + 1] + g[tx + 3], w2 * g[tx + 2]));
        }
    }
    __syncthreads();

    // ---- Stage 3: vertical Gaussian (40 x 72) -> bufA (gray dead) ----
    {
        const int r0r = ty * 5;
        float2 h[9];
#pragma unroll
        for (int r = 0; r < 9; ++r) h[r] = ((const float2*)&s.bufB[(r0r + r) * 72])[tx];
#pragma unroll
        for (int v = 0; v < 5; ++v) {
            float2 o;
            o.x = fmaf(w0, h[v].x + h[v + 4].x, fmaf(w1, h[v + 1].x + h[v + 3].x, w2 * h[v + 2].x));
            o.y = fmaf(w0, h[v].y + h[v + 4].y, fmaf(w1, h[v + 1].y + h[v + 3].y, w2 * h[v + 2].y));
            ((float2*)&s.bufA[(r0r + v) * 72])[tx] = o;
        }
        if (tx < 8) {
            float hh[9];
#pragma unroll
            for (int r = 0; r < 9; ++r) hh[r] = s.bufB[(r0r + r) * 72 + 64 + tx];
#pragma unroll
            for (int v = 0; v < 5; ++v)
                s.bufA[(r0r + v) * 72 + 64 + tx] =
                    fmaf(w0, hh[v] + hh[v + 4], fmaf(w1, hh[v + 1] + hh[v + 3], w2 * hh[v + 2]));
        }
    }
    __syncthreads();

    // ---- Stage 4a: Sobel + mag + delta, cols 0..63 -> bufB (hblur dead) ----
    {
        const int r0m = min(ty * 5, 33);   // ragged tail: duplicate rows, harmless
        const int jb = 2 * tx;
        const int x = x0 - 3 + jb;
        bool xin0 = true, xin1 = true, lc0 = true, rc0 = true, lc1 = true, rc1 = true;
        if (BORDER) {
            xin0 = (unsigned)x < (unsigned)W;
            xin1 = (unsigned)(x + 1) < (unsigned)W;
            lc0 = (x > 0); rc0 = (x < W - 1);
            lc1 = (x + 1 > 0); rc1 = (x + 1 < W - 1);
        }
        float s0p, d0p, s1p, d1p, s0c, d0c, s1c, d1c;
#define LOADROW(R, S0, D0, S1, D1)                                             \
        {                                                                      \
            int rr;                                                            \
            if (BORDER) {                                                      \
                int yr = y0 - 3 + r0m + (R);                                   \
                yr = max(0, min(yr, H - 1));                                   \
                rr = yr - y0 + 4;                                              \
            } else {                                                           \
                rr = r0m + (R) + 1;                                            \
            }                                                                  \
            const float2* br = (const float2*)&s.bufA[rr * 72 + jb];           \
            float2 p = br[0], q = br[1];                                       \
            float l0 = BORDER ? (lc0 ? p.x : p.y) : p.x;                       \
            float r0_ = BORDER ? (rc0 ? q.x : p.y) : q.x;                      \
            float l1 = BORDER ? (lc1 ? p.y : q.x) : p.y;                       \
            float r1_ = BORDER ? (rc1 ? q.y : q.x) : q.y;                      \
            S0 = l0 + 2.0f * p.y + r0_; D0 = r0_ - l0;                         \
            S1 = l1 + 2.0f * q.x + r1_; D1 = r1_ - l1;                         \
        }
        LOADROW(-1, s0p, d0p, s1p, d1p)
        LOADROW(0, s0c, d0c, s1c, d1c)
#pragma unroll
        for (int v = 0; v < 5; ++v) {
            float s0n, d0n, s1n, d1n;
            LOADROW(v + 1, s0n, d0n, s1n, d1n)
            const int i = r0m + v;
            float gy0 = (s0n - s0p) * 0.125f;
            float gx0 = (d0p + 2.0f * d0c + d0n) * 0.125f;
            float gy1 = (s1n - s1p) * 0.125f;
            float gx1 = (d1p + 2.0f * d1c + d1n) * 0.125f;

            float m0 = 0.0f, m1 = 0.0f;
            short e0 = 1, e1 = 1;
            if (BORDER) {
                bool yin = (unsigned)(y0 - 3 + i) < (unsigned)H;
                if (yin && xin0) mag_sector(gx0, gy0, m0, e0);
                if (yin && xin1) mag_sector(gx1, gy1, m1, e1);
            } else {
                mag_sector(gx0, gy0, m0, e0);
                mag_sector(gx1, gy1, m1, e1);
            }
            *(float2*)&s.bufB[i * 72 + jb] = make_float2(m0, m1);
            *(short2*)&s.sDel[i * 72 + jb] = make_short2(e0, e1);

            s0p = s0c; d0p = d0c; s1p = s1c; d1p = d1c;
            s0c = s0n; d0c = d0n; s1c = s1n; d1c = d1n;
        }
#undef LOADROW
    }

    // ---- Stage 4b: cols 64..69 as flat tasks (38 rows x 3 float2 = 114) ----
    if (tid < 114) {
        const int i = tid / 3;
        const int c = tid - 3 * i;
        const int jb = 64 + 2 * c;
        float m0 = 0.0f, m1 = 0.0f;
        short e0 = 1, e1 = 1;
        if (BORDER) {
            const int y = y0 - 3 + i;
            if ((unsigned)y < (unsigned)H) {
                int ymi = max(y - 1, 0) - (y0 - 4);
                int ypi = min(y + 1, H - 1) - (y0 - 4);
                int yci = i + 1;
#pragma unroll
                for (int k = 0; k < 2; ++k) {
                    int xk = x0 - 3 + jb + k;
                    if ((unsigned)xk < (unsigned)W) {
                        int xm = max(xk - 1, 0) - (x0 - 4);
                        int xp = min(xk + 1, W - 1) - (x0 - 4);
                        int xc = jb + 1 + k;
                        float b00 = s.bufA[ymi * 72 + xm], b01 = s.bufA[ymi * 72 + xc], b02 = s.bufA[ymi * 72 + xp];
                        float b10 = s.bufA[yci * 72 + xm],                              b12 = s.bufA[yci * 72 + xp];
                        float b20 = s.bufA[ypi * 72 + xm], b21 = s.bufA[ypi * 72 + xc], b22 = s.bufA[ypi * 72 + xp];
                        float gx = ((b02 - b00) + 2.0f * (b12 - b10) + (b22 - b20)) * 0.125f;
                        float gy = ((b20 - b00) + 2.0f * (b21 - b01) + (b22 - b02)) * 0.125f;
                        if (k == 0) mag_sector(gx, gy, m0, e0);
                        else        mag_sector(gx, gy, m1, e1);
                    }
                }
            }
        } else {
            const float2* rU = (const float2*)&s.bufA[i * 72 + jb];
            const float2* rC = (const float2*)&s.bufA[(i + 1) * 72 + jb];
            const float2* rD = (const float2*)&s.bufA[(i + 2) * 72 + jb];
            float2 u01 = rU[0], u23 = rU[1];
            float2 c01 = rC[0], c23 = rC[1];
            float2 d01 = rD[0], d23 = rD[1];
            float gx0 = ((u23.x - u01.x) + 2.0f * (c23.x - c01.x) + (d23.x - d01.x)) * 0.125f;
            float gy0 = ((d01.x - u01.x) + 2.0f * (d01.y - u01.y) + (d23.x - u23.x)) * 0.125f;
            float gx1 = ((u23.y - u01.y) + 2.0f * (c23.y - c01.y) + (d23.y - d01.y)) * 0.125f;
            float gy1 = ((d01.y - u01.y) + 2.0f * (d23.x - u23.x) + (d23.y - u23.y)) * 0.125f;
            mag_sector(gx0, gy0, m0, e0);
            mag_sector(gx1, gy1, m1, e1);
        }
        *(float2*)&s.bufB[i * 72 + jb] = make_float2(m0, m1);
        *(short2*)&s.sDel[i * 72 + jb] = make_short2(e0, e1);
    }
    __syncthreads();

    // ---- Stage 5: NMS mask (36 x 68) -> bufA (blur dead) ----
    for (int i = ty; i < 36; i += 8) {
        bool yin = true;
        if (BORDER) yin = (unsigned)(y0 - 2 + i) < (unsigned)H;
#pragma unroll
        for (int jj = 0; jj < 3; ++jj) {
            int j = tx + jj * 32;
            if (jj < 2 || tx < 4) {
                float m = 0.0f;
                bool ok = true;
                if (BORDER) ok = yin && (unsigned)(x0 - 2 + j) < (unsigned)W;
                if (ok) {
                    int ci = (i + 1) * 72 + j + 1;
                    int d = s.sDel[ci];
                    float c = s.bufB[ci];
                    float p1 = s.bufB[ci + d];
                    float p2 = s.bufB[ci - d];
                    m = (c > p1 && c > p2) ? c : 0.0f;
                }
                s.bufA[i * 72 + j] = m;
            }
        }
    }
    __syncthreads();

    // ---- Stage 6: horizontal 5-max (36 x 64), float4 -> bufB (mag dead) ----
    {
        const int half = tx >> 4;
        const int q4 = (tx & 15) * 4;
        for (int r = ty; r < 18; r += 8) {
            const int i = half * 18 + r;
            float4 A = *(const float4*)&s.bufA[i * 72 + q4];
            float4 B = *(const float4*)&s.bufA[i * 72 + q4 + 4];
            float m  = fmaxf(A.w, B.x);
            float t1 = fmaxf(A.y, A.z);
            float t2 = fmaxf(B.y, B.z);
            float4 o;
            o.x = fmaxf(m, fmaxf(A.x, t1));
            o.y = fmaxf(m, fmaxf(t1, B.y));
            o.z = fmaxf(m, fmaxf(A.z, t2));
            o.w = fmaxf(m, fmaxf(t2, B.w));
            *(float4*)&s.bufB[i * 64 + q4] = o;
        }
    }
    __syncthreads();

    // ---- Stage 7: vertical 5-max, 4 contiguous rows/thread, float2 STG ----
    {
        const int r0o = ty * 4;
        float2 t[8];
#pragma unroll
        for (int r = 0; r < 8; ++r) t[r] = ((const float2*)&s.bufB[(r0o + r) * 64])[tx];
#pragma unroll
        for (int v = 0; v < 4; ++v) {
            float cx = fmaxf(fmaxf(t[v + 1].x, t[v + 2].x), fmaxf(t[v + 3].x, t[v + 4].x));
            float cy = fmaxf(fmaxf(t[v + 1].y, t[v + 2].y), fmaxf(t[v + 3].y, t[v + 4].y));
            float2 o = make_float2(fmaxf(cx, t[v].x), fmaxf(cy, t[v].y));
            *(float2*)&ob[(size_t)(y0 + r0o + v) * W + x0 + 2 * tx] = o;
        }
    }
}

__global__ __launch_bounds__(256, 6) void canny_fused_kernel(
    const float* __restrict__ in, float* __restrict__ out) {
    __shared__ Smem s;
    const int bx = blockIdx.x, by = blockIdx.y;
    const int x0 = bx * 64, y0 = by * 32;
    const float* base = in + (size_t)blockIdx.z * 3 * PLANE;
    float* ob = out + (size_t)blockIdx.z * PLANE;
    const int tx = threadIdx.x & 31;
    const int ty = threadIdx.x >> 5;

    if (bx == 0 || bx == 7 || by == 0 || by == 15)
        canny_tile<true>(s, base, ob, x0, y0, tx, ty, threadIdx.x);
    else
        canny_tile<false>(s, base, ob, x0, y0, tx, ty, threadIdx.x);
}

extern "C" void kernel_launch(void* const* d_in, const int* in_sizes, int n_in,
                              void* d_out, int out_size) {
    const float* x = (const float*)d_in[0];
    float* out = (float*)d_out;
    dim3 grid(W / 64, H / 32, 32);
    canny_fused_kernel<<<grid, 256>>>(x, out);
}

// round 11
// speedup vs baseline: 1.4105x; 1.0005x over previous
#include <cuda_runtime.h>

// Fused Canny-NMS-dilate for (32,3,512,512) fp32 -> (32,1,512,512) fp32.
// 64x64 output tile, 512 threads (32x16), all-warp stages, two-buffer
// aliasing in dynamic smem (~49KB), float4 blur stages.

#define H 512
#define W 512
#define PLANE (512 * 512)

// Region geometry (rows x cols, stride in floats):
//  bufA: gray 76x76 (stride 76) -> blur 72x72 (stride 72) -> mask 68x68 (stride 72)
//  bufB: hblur 76x72 (stride 72) -> mag 70x70 (stride 72) -> rowmax 68x64 (stride 64)
//  sDel: 70x72 int8 (NMS neighbor offset, sign-free; values 1/71/72/73)
#define BUFA_FLOATS (76 * 76)
#define BUFB_FLOATS (76 * 72)
#define SDEL_BYTES  (70 * 72)
#define SMEM_BYTES  (BUFA_FLOATS * 4 + BUFB_FLOATS * 4 + SDEL_BYTES)

__device__ __forceinline__ void mag_sector(float gx, float gy, float& m, signed char& e) {
    m = sqrtf(fmaf(gx, gx, fmaf(gy, gy, 1e-6f)));
    float ax = fabsf(gx), ay = fabsf(gy);
    if (ay <= 0.41421356237309503f * ax)      e = 1;    // horizontal
    else if (ay >= 2.4142135623730951f * ax)  e = 72;   // vertical
    else e = ((gx > 0.0f) == (gy > 0.0f)) ? 73 : 71;    // diagonals
}

template <bool BORDER>
__device__ __forceinline__ void canny_tile(
    float* __restrict__ bufA, float* __restrict__ bufB, signed char* __restrict__ sDel,
    const float* __restrict__ base, float* __restrict__ ob,
    int x0, int y0, int tx, int ty, int tid) {

    const float w0 = 0.054488684549642945f;
    const float w1 = 0.24420134200323337f;
    const float w2 = 0.4026199485882447f;

    // ---- Stage 1: gray (76 x 76) -> bufA stride 76 ----
    if (BORDER) {
        int xs0, xs1, xs2;
        int x = x0 - 6 + tx; x = (x < 0) ? -x : x; xs0 = (x > 511) ? 1022 - x : x;
        x = x0 + 26 + tx;                           xs1 = (x > 511) ? 1022 - x : x;
        x = x0 + 58 + tx;                           xs2 = (x > 511) ? 1022 - x : x;
        for (int i = ty; i < 76; i += 16) {
            int y = y0 - 6 + i; y = (y < 0) ? -y : y; y = (y > 511) ? 1022 - y : y;
            const float* r0 = base + y * W;
            float* gr = &bufA[i * 76];
            gr[tx]      = fmaf(0.299f, r0[2 * PLANE + xs0], fmaf(0.587f, r0[PLANE + xs0], 0.114f * r0[xs0]));
            gr[tx + 32] = fmaf(0.299f, r0[2 * PLANE + xs1], fmaf(0.587f, r0[PLANE + xs1], 0.114f * r0[xs1]));
            if (tx < 12)
                gr[tx + 64] = fmaf(0.299f, r0[2 * PLANE + xs2], fmaf(0.587f, r0[PLANE + xs2], 0.114f * r0[xs2]));
        }
    } else {
        for (int i = ty; i < 76; i += 16) {
            const float* r0 = base + (y0 - 6 + i) * W + (x0 - 6);
            float2* gr = (float2*)&bufA[i * 76];
            {
                float2 b = *(const float2*)(r0 + 2 * tx);
                float2 g = *(const float2*)(r0 + PLANE + 2 * tx);
                float2 r = *(const float2*)(r0 + 2 * PLANE + 2 * tx);
                gr[tx] = make_float2(fmaf(0.299f, r.x, fmaf(0.587f, g.x, 0.114f * b.x)),
                                     fmaf(0.299f, r.y, fmaf(0.587f, g.y, 0.114f * b.y)));
            }
            if (tx < 6) {
                float2 b = *(const float2*)(r0 + 64 + 2 * tx);
                float2 g = *(const float2*)(r0 + PLANE + 64 + 2 * tx);
                float2 r = *(const float2*)(r0 + 2 * PLANE + 64 + 2 * tx);
                gr[32 + tx] = make_float2(fmaf(0.299f, r.x, fmaf(0.587f, g.x, 0.114f * b.x)),
                                          fmaf(0.299f, r.y, fmaf(0.587f, g.y, 0.114f * b.y)));
            }
        }
    }
    __syncthreads();

    // ---- Stage 2: horizontal Gaussian (76 x 72) -> bufB, float4 (18 tasks/row) ----
    for (unsigned idx = tid; idx < 76 * 18; idx += 512) {
        unsigned i = idx / 18u;
        unsigned c = idx - 18u * i;
        const float* g = &bufA[i * 76 + 4 * c];
        float4 g0 = *(const float4*)g;
        float4 g1 = *(const float4*)(g + 4);
        float4 o;
        o.x = fmaf(w0, g0.x + g1.x, fmaf(w1, g0.y + g0.w, w2 * g0.z));
        o.y = fmaf(w0, g0.y + g1.y, fmaf(w1, g0.z + g1.x, w2 * g0.w));
        o.z = fmaf(w0, g0.z + g1.z, fmaf(w1, g0.w + g1.y, w2 * g1.x));
        o.w = fmaf(w0, g0.w + g1.w, fmaf(w1, g1.x + g1.z, w2 * g1.y));
        *(float4*)&bufB[i * 72 + 4 * c] = o;
    }
    __syncthreads();

    // ---- Stage 3: vertical Gaussian (72 x 72) -> bufA, float4, 18 lanes ----
    if (tx < 18) {
        const int r0r = min(ty * 5, 67);
        const int c4 = 4 * tx;
        float4 win[5];
#pragma unroll
        for (int k = 0; k < 9; ++k) {
            float4 h = *(const float4*)&bufB[(r0r + k) * 72 + c4];
            win[k % 5] = h;
            if (k >= 4) {
                float4 a = win[(k - 4) % 5], b = win[(k - 3) % 5];
                float4 cc = win[(k - 2) % 5], d = win[(k - 1) % 5];
                float4 o;
                o.x = fmaf(w0, a.x + h.x, fmaf(w1, b.x + d.x, w2 * cc.x));
                o.y = fmaf(w0, a.y + h.y, fmaf(w1, b.y + d.y, w2 * cc.y));
                o.z = fmaf(w0, a.z + h.z, fmaf(w1, b.z + d.z, w2 * cc.z));
                o.w = fmaf(w0, a.w + h.w, fmaf(w1, b.w + d.w, w2 * cc.w));
                *(float4*)&bufA[(r0r + k - 4) * 72 + c4] = o;
            }
        }
    }
    __syncthreads();

    // ---- Stage 4a: Sobel + mag + delta, cols 0..63 -> bufB/sDel ----
    {
        const int r0m = min(ty * 5, 65);
        const int jb = 2 * tx;
        const int x = x0 - 3 + jb;
        bool xin0 = true, xin1 = true, lc0 = true, rc0 = true, lc1 = true, rc1 = true;
        if (BORDER) {
            xin0 = (unsigned)x < (unsigned)W;
            xin1 = (unsigned)(x + 1) < (unsigned)W;
            lc0 = (x > 0); rc0 = (x < W - 1);
            lc1 = (x + 1 > 0); rc1 = (x + 1 < W - 1);
        }
        float s0p, d0p, s1p, d1p, s0c, d0c, s1c, d1c;
#define LOADROW(R, S0, D0, S1, D1)                                             \
        {                                                                      \
            int rr;                                                            \
            if (BORDER) {                                                      \
                int yr = y0 - 3 + r0m + (R);                                   \
                yr = max(0, min(yr, H - 1));                                   \
                rr = yr - y0 + 4;                                              \
            } else {                                                           \
                rr = r0m + (R) + 1;                                            \
            }                                                                  \
            const float2* br = (const float2*)&bufA[rr * 72 + jb];             \
            float2 p = br[0], q = br[1];                                       \
            float l0 = BORDER ? (lc0 ? p.x : p.y) : p.x;                       \
            float r0_ = BORDER ? (rc0 ? q.x : p.y) : q.x;                      \
            float l1 = BORDER ? (lc1 ? p.y : q.x) : p.y;                       \
            float r1_ = BORDER ? (rc1 ? q.y : q.x) : q.y;                      \
            S0 = l0 + 2.0f * p.y + r0_; D0 = r0_ - l0;                         \
            S1 = l1 + 2.0f * q.x + r1_; D1 = r1_ - l1;                         \
        }
        LOADROW(-1, s0p, d0p, s1p, d1p)
        LOADROW(0, s0c, d0c, s1c, d1c)
#pragma unroll
        for (int v = 0; v < 5; ++v) {
            float s0n, d0n, s1n, d1n;
            LOADROW(v + 1, s0n, d0n, s1n, d1n)
            const int i = r0m + v;
            float gy0 = (s0n - s0p) * 0.125f;
            float gx0 = (d0p + 2.0f * d0c + d0n) * 0.125f;
            float gy1 = (s1n - s1p) * 0.125f;
            float gx1 = (d1p + 2.0f * d1c + d1n) * 0.125f;

            float m0 = 0.0f, m1 = 0.0f;
            signed char e0 = 1, e1 = 1;
            if (BORDER) {
                bool yin = (unsigned)(y0 - 3 + i) < (unsigned)H;
                if (yin && xin0) mag_sector(gx0, gy0, m0, e0);
                if (yin && xin1) mag_sector(gx1, gy1, m1, e1);
            } else {
                mag_sector(gx0, gy0, m0, e0);
                mag_sector(gx1, gy1, m1, e1);
            }
            *(float2*)&bufB[i * 72 + jb] = make_float2(m0, m1);
            *(char2*)&sDel[i * 72 + jb] = make_char2(e0, e1);

            s0p = s0c; d0p = d0c; s1p = s1c; d1p = d1c;
            s0c = s0n; d0c = d0n; s1c = s1n; d1c = d1n;
        }
#undef LOADROW
    }

    // ---- Stage 4b: cols 64..69 as flat tasks (70 rows x 3 float2 = 210) ----
    if (tid < 210) {
        const int i = tid / 3;
        const int c = tid - 3 * i;
        const int jb = 64 + 2 * c;
        float m0 = 0.0f, m1 = 0.0f;
        signed char e0 = 1, e1 = 1;
        if (BORDER) {
            const int y = y0 - 3 + i;
            if ((unsigned)y < (unsigned)H) {
                int ymi = max(y - 1, 0) - (y0 - 4);
                int ypi = min(y + 1, H - 1) - (y0 - 4);
                int yci = i + 1;
#pragma unroll
                for (int k = 0; k < 2; ++k) {
                    int xk = x0 - 3 + jb + k;
                    if ((unsigned)xk < (unsigned)W) {
                        int xm = max(xk - 1, 0) - (x0 - 4);
                        int xp = min(xk + 1, W - 1) - (x0 - 4);
                        int xc = jb + 1 + k;
                        float b00 = bufA[ymi * 72 + xm], b01 = bufA[ymi * 72 + xc], b02 = bufA[ymi * 72 + xp];
                        float b10 = bufA[yci * 72 + xm],                            b12 = bufA[yci * 72 + xp];
                        float b20 = bufA[ypi * 72 + xm], b21 = bufA[ypi * 72 + xc], b22 = bufA[ypi * 72 + xp];
                        float gx = ((b02 - b00) + 2.0f * (b12 - b10) + (b22 - b20)) * 0.125f;
                        float gy = ((b20 - b00) + 2.0f * (b21 - b01) + (b22 - b02)) * 0.125f;
                        if (k == 0) mag_sector(gx, gy, m0, e0);
                        else        mag_sector(gx, gy, m1, e1);
                    }
                }
            }
        } else {
            const float2* rU = (const float2*)&bufA[i * 72 + jb];
            const float2* rC = (const float2*)&bufA[(i + 1) * 72 + jb];
            const float2* rD = (const float2*)&bufA[(i + 2) * 72 + jb];
            float2 u01 = rU[0], u23 = rU[1];
            float2 c01 = rC[0], c23 = rC[1];
            float2 d01 = rD[0], d23 = rD[1];
            float gx0 = ((u23.x - u01.x) + 2.0f * (c23.x - c01.x) + (d23.x - d01.x)) * 0.125f;
            float gy0 = ((d01.x - u01.x) + 2.0f * (d01.y - u01.y) + (d23.x - u23.x)) * 0.125f;
            float gx1 = ((u23.y - u01.y) + 2.0f * (c23.y - c01.y) + (d23.y - d01.y)) * 0.125f;
            float gy1 = ((d01.y - u01.y) + 2.0f * (d23.x - u23.x) + (d23.y - u23.y)) * 0.125f;
            mag_sector(gx0, gy0, m0, e0);
            mag_sector(gx1, gy1, m1, e1);
        }
        *(float2*)&bufB[i * 72 + jb] = make_float2(m0, m1);
        *(char2*)&sDel[i * 72 + jb] = make_char2(e0, e1);
    }
    __syncthreads();

    // ---- Stage 5: NMS mask (68 x 68) -> bufA (blur dead) ----
    for (int i = ty; i < 68; i += 16) {
        bool yin = true;
        if (BORDER) yin = (unsigned)(y0 - 2 + i) < (unsigned)H;
#pragma unroll
        for (int jj = 0; jj < 3; ++jj) {
            int j = tx + jj * 32;
            if (jj < 2 || tx < 4) {
                float m = 0.0f;
                bool ok = true;
                if (BORDER) ok = yin && (unsigned)(x0 - 2 + j) < (unsigned)W;
                if (ok) {
                    int ci = (i + 1) * 72 + j + 1;
                    int d = sDel[ci];
                    float c = bufB[ci];
                    float p1 = bufB[ci + d];
                    float p2 = bufB[ci - d];
                    m = (c > p1 && c > p2) ? c : 0.0f;
                }
                bufA[i * 72 + j] = m;
            }
        }
    }
    __syncthreads();

    // ---- Stage 6: horizontal 5-max (68 x 64), float4 -> bufB (mag dead) ----
    {
        const int half = tx >> 4;
        const int q4 = (tx & 15) * 4;
        for (int r = ty; r < 34; r += 16) {
            const int i = half * 34 + r;
            float4 A = *(const float4*)&bufA[i * 72 + q4];
            float4 B = *(const float4*)&bufA[i * 72 + q4 + 4];
            float m  = fmaxf(A.w, B.x);
            float t1 = fmaxf(A.y, A.z);
            float t2 = fmaxf(B.y, B.z);
            float4 o;
            o.x = fmaxf(m, fmaxf(A.x, t1));
            o.y = fmaxf(m, fmaxf(t1, B.y));
            o.z = fmaxf(m, fmaxf(A.z, t2));
            o.w = fmaxf(m, fmaxf(t2, B.w));
            *(float4*)&bufB[i * 64 + q4] = o;
        }
    }
    __syncthreads();

    // ---- Stage 7: vertical 5-max, 4 contiguous rows/thread, float2 STG ----
    {
        const int r0o = ty * 4;
        float2 t[8];
#pragma unroll
        for (int r = 0; r < 8; ++r) t[r] = ((const float2*)&bufB[(r0o + r) * 64])[tx];
#pragma unroll
        for (int v = 0; v < 4; ++v) {
            float cx = fmaxf(fmaxf(t[v + 1].x, t[v + 2].x), fmaxf(t[v + 3].x, t[v + 4].x));
            float cy = fmaxf(fmaxf(t[v + 1].y, t[v + 2].y), fmaxf(t[v + 3].y, t[v + 4].y));
            float2 o = make_float2(fmaxf(cx, t[v].x), fmaxf(cy, t[v].y));
            *(float2*)&ob[(size_t)(y0 + r0o + v) * W + x0 + 2 * tx] = o;
        }
    }
}

__global__ __launch_bounds__(512, 3) void canny_fused_kernel(
    const float* __restrict__ in, float* __restrict__ out) {
    extern __shared__ char dsm[];
    float* bufA = (float*)dsm;
    float* bufB = bufA + BUFA_FLOATS;
    signed char* sDel = (signed char*)(bufB + BUFB_FLOATS);

    const int bx = blockIdx.x, by = blockIdx.y;
    const int x0 = bx * 64, y0 = by * 64;
    const float* base = in + (size_t)blockIdx.z * 3 * PLANE;
    float* ob = out + (size_t)blockIdx.z * PLANE;
    const int tx = threadIdx.x & 31;
    const int ty = threadIdx.x >> 5;

    if (bx == 0 || bx == 7 || by == 0 || by == 7)
        canny_tile<true>(bufA, bufB, sDel, base, ob, x0, y0, tx, ty, threadIdx.x);
    else
        canny_tile<false>(bufA, bufB, sDel, base, ob, x0, y0, tx, ty, threadIdx.x);
}

extern "C" void kernel_launch(void* const* d_in, const int* in_sizes, int n_in,
                              void* d_out, int out_size) {
    const float* x = (const float*)d_in[0];
    float* out = (float*)d_out;
    cudaFuncSetAttribute(canny_fused_kernel,
                         cudaFuncAttributeMaxDynamicSharedMemorySize, SMEM_BYTES);
    dim3 grid(W / 64, H / 64, 32);
    canny_fused_kernel<<<grid, 512, SMEM_BYTES>>>(x, out);
}

// round 13
// speedup vs baseline: 1.4216x; 1.0079x over previous
#include <cuda_runtime.h>

// Fused Canny-NMS-dilate for (32,3,512,512) fp32 -> (32,1,512,512) fp32.
// 64x64 output tile, 512 threads (32x16), dynamic smem (~49KB),
// launch_bounds(512,4) -> 4 blocks/SM (64 resident warps).

#define H 512
#define W 512
#define PLANE (512 * 512)

// Region geometry (rows x cols, stride in floats):
//  bufA: gray 76x76 (stride 76) -> blur 72x72 (stride 72) -> mask 68x68 (stride 72)
//  bufB: hblur 76x72 (stride 72) -> mag 70x70 (stride 72) -> rowmax 68x64 (stride 64)
//  sDel: 70x72 int8 (NMS neighbor offset, sign-free; values 1/71/72/73)
#define BUFA_FLOATS (76 * 76)
#define BUFB_FLOATS (76 * 72)
#define SDEL_BYTES  (70 * 72)
#define SMEM_BYTES  (BUFA_FLOATS * 4 + BUFB_FLOATS * 4 + SDEL_BYTES)

__device__ __forceinline__ void mag_sector(float gx, float gy, float& m, signed char& e) {
    m = sqrtf(fmaf(gx, gx, fmaf(gy, gy, 1e-6f)));
    float ax = fabsf(gx), ay = fabsf(gy);
    if (ay <= 0.41421356237309503f * ax)      e = 1;    // horizontal
    else if (ay >= 2.4142135623730951f * ax)  e = 72;   // vertical
    else e = ((gx > 0.0f) == (gy > 0.0f)) ? 73 : 71;    // diagonals
}

template <bool BORDER>
__device__ __forceinline__ void canny_tile(
    float* __restrict__ bufA, float* __restrict__ bufB, signed char* __restrict__ sDel,
    const float* __restrict__ base, float* __restrict__ ob,
    int x0, int y0, int tx, int ty, int tid) {

    const float w0 = 0.054488684549642945f;
    const float w1 = 0.24420134200323337f;
    const float w2 = 0.4026199485882447f;

    // ---- Stage 1: gray (76 x 76) -> bufA stride 76 ----
    if (BORDER) {
        int xs0, xs1, xs2;
        int x = x0 - 6 + tx; x = (x < 0) ? -x : x; xs0 = (x > 511) ? 1022 - x : x;
        x = x0 + 26 + tx;                           xs1 = (x > 511) ? 1022 - x : x;
        x = x0 + 58 + tx;                           xs2 = (x > 511) ? 1022 - x : x;
        for (int i = ty; i < 76; i += 16) {
            int y = y0 - 6 + i; y = (y < 0) ? -y : y; y = (y > 511) ? 1022 - y : y;
            const float* r0 = base + y * W;
            float* gr = &bufA[i * 76];
            gr[tx]      = fmaf(0.299f, r0[2 * PLANE + xs0], fmaf(0.587f, r0[PLANE + xs0], 0.114f * r0[xs0]));
            gr[tx + 32] = fmaf(0.299f, r0[2 * PLANE + xs1], fmaf(0.587f, r0[PLANE + xs1], 0.114f * r0[xs1]));
            if (tx < 12)
                gr[tx + 64] = fmaf(0.299f, r0[2 * PLANE + xs2], fmaf(0.587f, r0[PLANE + xs2], 0.114f * r0[xs2]));
        }
    } else {
        for (int i = ty; i < 76; i += 16) {
            const float* r0 = base + (y0 - 6 + i) * W + (x0 - 6);
            float2* gr = (float2*)&bufA[i * 76];
            {
                float2 b = *(const float2*)(r0 + 2 * tx);
                float2 g = *(const float2*)(r0 + PLANE + 2 * tx);
                float2 r = *(const float2*)(r0 + 2 * PLANE + 2 * tx);
                gr[tx] = make_float2(fmaf(0.299f, r.x, fmaf(0.587f, g.x, 0.114f * b.x)),
                                     fmaf(0.299f, r.y, fmaf(0.587f, g.y, 0.114f * b.y)));
            }
            if (tx < 6) {
                float2 b = *(const float2*)(r0 + 64 + 2 * tx);
                float2 g = *(const float2*)(r0 + PLANE + 64 + 2 * tx);
                float2 r = *(const float2*)(r0 + 2 * PLANE + 64 + 2 * tx);
                gr[32 + tx] = make_float2(fmaf(0.299f, r.x, fmaf(0.587f, g.x, 0.114f * b.x)),
                                          fmaf(0.299f, r.y, fmaf(0.587f, g.y, 0.114f * b.y)));
            }
        }
    }
    __syncthreads();

    // ---- Stage 2: horizontal Gaussian (76 x 72) -> bufB, float4 (18 tasks/row) ----
    for (unsigned idx = tid; idx < 76 * 18; idx += 512) {
        unsigned i = idx / 18u;
        unsigned c = idx - 18u * i;
        const float* g = &bufA[i * 76 + 4 * c];
        float4 g0 = *(const float4*)g;
        float4 g1 = *(const float4*)(g + 4);
        float4 o;
        o.x = fmaf(w0, g0.x + g1.x, fmaf(w1, g0.y + g0.w, w2 * g0.z));
        o.y = fmaf(w0, g0.y + g1.y, fmaf(w1, g0.z + g1.x, w2 * g0.w));
        o.z = fmaf(w0, g0.z + g1.z, fmaf(w1, g0.w + g1.y, w2 * g1.x));
        o.w = fmaf(w0, g0.w + g1.w, fmaf(w1, g1.x + g1.z, w2 * g1.y));
        *(float4*)&bufB[i * 72 + 4 * c] = o;
    }
    __syncthreads();

    // ---- Stage 3: vertical Gaussian (72 x 72) -> bufA, float4 ----
    // 432 flat tasks: 24 row-groups of 3 output rows x 18 float4 cols.
    if (tid < 432) {
        const unsigned g = (unsigned)tid / 18u;
        const unsigned c = (unsigned)tid - 18u * g;
        const int r0r = g * 3;
        const int c4 = 4 * c;
        float4 win[5];
#pragma unroll
        for (int k = 0; k < 7; ++k) {
            float4 h = *(const float4*)&bufB[(r0r + k) * 72 + c4];
            win[k % 5] = h;
            if (k >= 4) {
                float4 a = win[(k - 4) % 5], b = win[(k - 3) % 5];
                float4 cc = win[(k - 2) % 5], d = win[(k - 1) % 5];
                float4 o;
                o.x = fmaf(w0, a.x + h.x, fmaf(w1, b.x + d.x, w2 * cc.x));
                o.y = fmaf(w0, a.y + h.y, fmaf(w1, b.y + d.y, w2 * cc.y));
                o.z = fmaf(w0, a.z + h.z, fmaf(w1, b.z + d.z, w2 * cc.z));
                o.w = fmaf(w0, a.w + h.w, fmaf(w1, b.w + d.w, w2 * cc.w));
                *(float4*)&bufA[(r0r + k - 4) * 72 + c4] = o;
            }
        }
    }
    __syncthreads();

    // ---- Stage 4a: Sobel + mag + delta, cols 0..63 -> bufB/sDel ----
    {
        const int r0m = min(ty * 5, 65);   // ragged tail: duplicate rows, harmless
        const int jb = 2 * tx;
        const int x = x0 - 3 + jb;
        bool xin0 = true, xin1 = true, lc0 = true, rc0 = true, lc1 = true, rc1 = true;
        if (BORDER) {
            xin0 = (unsigned)x < (unsigned)W;
            xin1 = (unsigned)(x + 1) < (unsigned)W;
            lc0 = (x > 0); rc0 = (x < W - 1);
            lc1 = (x + 1 > 0); rc1 = (x + 1 < W - 1);
        }
        float s0p, d0p, s1p, d1p, s0c, d0c, s1c, d1c;
#define LOADROW(R, S0, D0, S1, D1)                                             \
        {                                                                      \
            int rr;                                                            \
            if (BORDER) {                                                      \
                int yr = y0 - 3 + r0m + (R);                                   \
                yr = max(0, min(yr, H - 1));                                   \
                rr = yr - y0 + 4;                                              \
            } else {                                                           \
                rr = r0m + (R) + 1;                                            \
            }                                                                  \
            const float2* br = (const float2*)&bufA[rr * 72 + jb];             \
            float2 p = br[0], q = br[1];                                       \
            float l0 = BORDER ? (lc0 ? p.x : p.y) : p.x;                       \
            float r0_ = BORDER ? (rc0 ? q.x : p.y) : q.x;                      \
            float l1 = BORDER ? (lc1 ? p.y : q.x) : p.y;                       \
            float r1_ = BORDER ? (rc1 ? q.y : q.x) : q.y;                      \
            S0 = l0 + 2.0f * p.y + r0_; D0 = r0_ - l0;                         \
            S1 = l1 + 2.0f * q.x + r1_; D1 = r1_ - l1;                         \
        }
        LOADROW(-1, s0p, d0p, s1p, d1p)
        LOADROW(0, s0c, d0c, s1c, d1c)
#pragma unroll
        for (int v = 0; v < 5; ++v) {
            float s0n, d0n, s1n, d1n;
            LOADROW(v + 1, s0n, d0n, s1n, d1n)
            const int i = r0m + v;
            float gy0 = (s0n - s0p) * 0.125f;
            float gx0 = (d0p + 2.0f * d0c + d0n) * 0.125f;
            float gy1 = (s1n - s1p) * 0.125f;
            float gx1 = (d1p + 2.0f * d1c + d1n) * 0.125f;

            float m0 = 0.0f, m1 = 0.0f;
            signed char e0 = 1, e1 = 1;
            if (BORDER) {
                bool yin = (unsigned)(y0 - 3 + i) < (unsigned)H;
                if (yin && xin0) mag_sector(gx0, gy0, m0, e0);
                if (yin && xin1) mag_sector(gx1, gy1, m1, e1);
            } else {
                mag_sector(gx0, gy0, m0, e0);
                mag_sector(gx1, gy1, m1, e1);
            }
            *(float2*)&bufB[i * 72 + jb] = make_float2(m0, m1);
            *(char2*)&sDel[i * 72 + jb] = make_char2(e0, e1);

            s0p = s0c; d0p = d0c; s1p = s1c; d1p = d1c;
            s0c = s0n; d0c = d0n; s1c = s1n; d1c = d1n;
        }
#undef LOADROW
    }

    // ---- Stage 4b: cols 64..69 as flat tasks (70 rows x 3 float2 = 210) ----
    if (tid < 210) {
        const int i = tid / 3;
        const int c = tid - 3 * i;
        const int jb = 64 + 2 * c;
        float m0 = 0.0f, m1 = 0.0f;
        signed char e0 = 1, e1 = 1;
        if (BORDER) {
            const int y = y0 - 3 + i;
            if ((unsigned)y < (unsigned)H) {
                int ymi = max(y - 1, 0) - (y0 - 4);
                int ypi = min(y + 1, H - 1) - (y0 - 4);
                int yci = i + 1;
#pragma unroll
                for (int k = 0; k < 2; ++k) {
                    int xk = x0 - 3 + jb + k;
                    if ((unsigned)xk < (unsigned)W) {
                        int xm = max(xk - 1, 0) - (x0 - 4);
                        int xp = min(xk + 1, W - 1) - (x0 - 4);
                        int xc = jb + 1 + k;
                        float b00 = bufA[ymi * 72 + xm], b01 = bufA[ymi * 72 + xc], b02 = bufA[ymi * 72 + xp];
                        float b10 = bufA[yci * 72 + xm],                            b12 = bufA[yci * 72 + xp];
                        float b20 = bufA[ypi * 72 + xm], b21 = bufA[ypi * 72 + xc], b22 = bufA[ypi * 72 + xp];
                        float gx = ((b02 - b00) + 2.0f * (b12 - b10) + (b22 - b20)) * 0.125f;
                        float gy = ((b20 - b00) + 2.0f * (b21 - b01) + (b22 - b02)) * 0.125f;
                        if (k == 0) mag_sector(gx, gy, m0, e0);
                        else        mag_sector(gx, gy, m1, e1);
                    }
                }
            }
        } else {
            const float2* rU = (const float2*)&bufA[i * 72 + jb];
            const float2* rC = (const float2*)&bufA[(i + 1) * 72 + jb];
            const float2* rD = (const float2*)&bufA[(i + 2) * 72 + jb];
            float2 u01 = rU[0], u23 = rU[1];
            float2 c01 = rC[0], c23 = rC[1];
            float2 d01 = rD[0], d23 = rD[1];
            float gx0 = ((u23.x - u01.x) + 2.0f * (c23.x - c01.x) + (d23.x - d01.x)) * 0.125f;
            float gy0 = ((d01.x - u01.x) + 2.0f * (d01.y - u01.y) + (d23.x - u23.x)) * 0.125f;
            float gx1 = ((u23.y - u01.y) + 2.0f * (c23.y - c01.y) + (d23.y - d01.y)) * 0.125f;
            float gy1 = ((d01.y - u01.y) + 2.0f * (d23.x - u23.x) + (d23.y - u23.y)) * 0.125f;
            mag_sector(gx0, gy0, m0, e0);
            mag_sector(gx1, gy1, m1, e1);
        }
        *(float2*)&bufB[i * 72 + jb] = make_float2(m0, m1);
        *(char2*)&sDel[i * 72 + jb] = make_char2(e0, e1);
    }
    __syncthreads();

    // ---- Stage 5: NMS mask (68 x 68) -> bufA (blur dead) ----
    for (int i = ty; i < 68; i += 16) {
        bool yin = true;
        if (BORDER) yin = (unsigned)(y0 - 2 + i) < (unsigned)H;
#pragma unroll
        for (int jj = 0; jj < 3; ++jj) {
            int j = tx + jj * 32;
            if (jj < 2 || tx < 4) {
                float m = 0.0f;
                bool ok = true;
                if (BORDER) ok = yin && (unsigned)(x0 - 2 + j) < (unsigned)W;
                if (ok) {
                    int ci = (i + 1) * 72 + j + 1;
                    int d = sDel[ci];
                    float c = bufB[ci];
                    float p1 = bufB[ci + d];
                    float p2 = bufB[ci - d];
                    m = (c > p1 && c > p2) ? c : 0.0f;
                }
                bufA[i * 72 + j] = m;
            }
        }
    }
    __syncthreads();

    // ---- Stage 6: horizontal 5-max (68 x 64), float4 -> bufB (mag dead) ----
    {
        const int half = tx >> 4;
        const int q4 = (tx & 15) * 4;
        for (int r = ty; r < 34; r += 16) {
            const int i = half * 34 + r;
            float4 A = *(const float4*)&bufA[i * 72 + q4];
            float4 B = *(const float4*)&bufA[i * 72 + q4 + 4];
            float m  = fmaxf(A.w, B.x);
            float t1 = fmaxf(A.y, A.z);
            float t2 = fmaxf(B.y, B.z);
            float4 o;
            o.x = fmaxf(m, fmaxf(A.x, t1));
            o.y = fmaxf(m, fmaxf(t1, B.y));
            o.z = fmaxf(m, fmaxf(A.z, t2));
            o.w = fmaxf(m, fmaxf(t2, B.w));
            *(float4*)&bufB[i * 64 + q4] = o;
        }
    }
    __syncthreads();

    // ---- Stage 7: vertical 5-max, 4 contiguous rows/thread, float2 STG ----
    {
        const int r0o = ty * 4;
        float2 t[8];
#pragma unroll
        for (int r = 0; r < 8; ++r) t[r] = ((const float2*)&bufB[(r0o + r) * 64])[tx];
#pragma unroll
        for (int v = 0; v < 4; ++v) {
            float cx = fmaxf(fmaxf(t[v + 1].x, t[v + 2].x), fmaxf(t[v + 3].x, t[v + 4].x));
            float cy = fmaxf(fmaxf(t[v + 1].y, t[v + 2].y), fmaxf(t[v + 3].y, t[v + 4].y));
            float2 o = make_float2(fmaxf(cx, t[v].x), fmaxf(cy, t[v].y));
            *(float2*)&ob[(size_t)(y0 + r0o + v) * W + x0 + 2 * tx] = o;
        }
    }
}

__global__ __launch_bounds__(512, 4) void canny_fused_kernel(
    const float* __restrict__ in, float* __restrict__ out) {
    extern __shared__ char dsm[];
    float* bufA = (float*)dsm;
    float* bufB = bufA + BUFA_FLOATS;
    signed char* sDel = (signed char*)(bufB + BUFB_FLOATS);

    const int bx = blockIdx.x, by = blockIdx.y;
    const int x0 = bx * 64, y0 = by * 64;
    const float* base = in + (size_t)blockIdx.z * 3 * PLANE;
    float* ob = out + (size_t)blockIdx.z * PLANE;
    const int tx = threadIdx.x & 31;
    const int ty = threadIdx.x >> 5;

    if (bx == 0 || bx == 7 || by == 0 || by == 7)
        canny_tile<true>(bufA, bufB, sDel, base, ob, x0, y0, tx, ty, threadIdx.x);
    else
        canny_tile<false>(bufA, bufB, sDel, base, ob, x0, y0, tx, ty, threadIdx.x);
}

extern "C" void kernel_launch(void* const* d_in, const int* in_sizes, int n_in,
                              void* d_out, int out_size) {
    const float* x = (const float*)d_in[0];
    float* out = (float*)d_out;
    cudaFuncSetAttribute(canny_fused_kernel,
                         cudaFuncAttributeMaxDynamicSharedMemorySize, SMEM_BYTES);
    dim3 grid(W / 64, H / 64, 32);
    canny_fused_kernel<<<grid, 512, SMEM_BYTES>>>(x, out);
}